// round 13
// baseline (speedup 1.0000x reference)
#include <cuda_runtime.h>
#include <cuda_fp16.h>
#include <math.h>

#define W_IMG 1024
#define N_PIX (W_IMG * W_IMG)
#define MAXB 8
#define NTH 256
#define NBLK_STAT 256   // 8 x 32 blocks per batch

// per-block partial stats: [b][block][16]
// [0..2]=sum q_c^2, [3..5]=sum k_c^2, [6..14]=sum q_c*k_d
__device__ float g_part[MAXB][NBLK_STAT][16];
// fp16 planar k scratch: [b][c][pix]  (48 MB)
__device__ __align__(16) __half g_k[(size_t)MAXB * 3 * N_PIX];

// ---------------------------------------------------------------------------
// k_stats: R6-proven 4x4 patch per thread. K path first (k emitted to fp16
// scratch + kout regs), then Q path accumulating the 15 stats.
// Per-block partials (no atomics, no zeroing, no finalize tail).
// ---------------------------------------------------------------------------
__global__ __launch_bounds__(NTH) void k_stats(const float* __restrict__ x,
                                               const float* __restrict__ fhigh,
                                               const float* __restrict__ qC,
                                               const float* __restrict__ qD,
                                               const float* __restrict__ kC,
                                               const float* __restrict__ kD) {
    __shared__ float red[NTH / 32][15];

    const int tid = threadIdx.x;
    const int b = blockIdx.z;
    const int warp = tid >> 5, lane = tid & 31;
    const int wx0 = blockIdx.x * 128;
    const int px0 = wx0 + lane * 4;
    const int y0 = blockIdx.y * 32 + warp * 4;

    const float* __restrict__ xb = x + (size_t)b * 3 * N_PIX;
    const float* __restrict__ fb = fhigh + (size_t)b * 3 * N_PIX;
    __half* __restrict__ gk = g_k + (size_t)b * 3 * N_PIX;

    const bool is_e = (lane == 0) | (lane == 31);
    const int ex = (lane == 0) ? wx0 - 1 : wx0 + 128;
    const bool ex_ok = (unsigned)ex < (unsigned)W_IMG;

    float p[15];
#pragma unroll
    for (int i = 0; i < 15; i++) p[i] = 0.f;

    float kout[3][4][4];  // [ch][row][j]

    // ================= K path (input x, channels-last) =================
    {
        float cw[9], dw[27];
#pragma unroll
        for (int i = 0; i < 9; i++) cw[i] = kC[i];
#pragma unroll
        for (int i = 0; i < 27; i++) dw[i] = kD[i];

        float a0[3][4], a1[3][4], a2[3][4];
#pragma unroll
        for (int c = 0; c < 3; c++)
#pragma unroll
            for (int j = 0; j < 4; j++) { a0[c][j] = a1[c][j] = a2[c][j] = 0.f; }

#pragma unroll
        for (int iy = 0; iy < 6; iy++) {
            const int yin = y0 + iy - 1;
            const bool yok = (unsigned)yin < (unsigned)W_IMG;

            float hm[3][4];
#pragma unroll
            for (int c = 0; c < 3; c++)
#pragma unroll
                for (int j = 0; j < 4; j++) hm[c][j] = 0.f;

            if (yok) {
                const float4* p4 = (const float4*)(xb + (size_t)(yin * W_IMG + px0) * 3);
                float4 v0 = p4[0], v1 = p4[1], v2 = p4[2];
                float g[4][3] = {{v0.x, v0.y, v0.z}, {v0.w, v1.x, v1.y},
                                 {v1.z, v1.w, v2.x}, {v2.y, v2.z, v2.w}};
#pragma unroll
                for (int j = 0; j < 4; j++)
#pragma unroll
                    for (int c = 0; c < 3; c++)
                        hm[c][j] = cw[c * 3] * g[j][0] + cw[c * 3 + 1] * g[j][1] + cw[c * 3 + 2] * g[j][2];
            }
            float he[3] = {0.f, 0.f, 0.f};
            if (yok && is_e && ex_ok) {
                const float* pe = xb + (size_t)(yin * W_IMG + ex) * 3;
                float g0 = pe[0], g1 = pe[1], g2 = pe[2];
#pragma unroll
                for (int c = 0; c < 3; c++)
                    he[c] = cw[c * 3] * g0 + cw[c * 3 + 1] * g1 + cw[c * 3 + 2] * g2;
            }
            float hl[3], hr[3];
#pragma unroll
            for (int c = 0; c < 3; c++) {
                hl[c] = __shfl_up_sync(0xffffffffu, hm[c][3], 1);
                hr[c] = __shfl_down_sync(0xffffffffu, hm[c][0], 1);
                if (lane == 0) hl[c] = he[c];
                if (lane == 31) hr[c] = he[c];
            }
#pragma unroll
            for (int c = 0; c < 3; c++)
#pragma unroll
                for (int j = 0; j < 4; j++) {
                    float L = j ? hm[c][j - 1] : hl[c];
                    float M_ = hm[c][j];
                    float R = (j < 3) ? hm[c][j + 1] : hr[c];
                    a0[c][j] += dw[c * 9 + 6] * L + dw[c * 9 + 7] * M_ + dw[c * 9 + 8] * R;
                    a1[c][j] += dw[c * 9 + 3] * L + dw[c * 9 + 4] * M_ + dw[c * 9 + 5] * R;
                    a2[c][j] += dw[c * 9 + 0] * L + dw[c * 9 + 1] * M_ + dw[c * 9 + 2] * R;
                }
            if (iy >= 2) {
                const int r = iy - 2;
                const int yout = y0 + r;
                const size_t o = (size_t)yout * W_IMG + px0;
#pragma unroll
                for (int c = 0; c < 3; c++) {
#pragma unroll
                    for (int j = 0; j < 4; j++) {
                        float v = a0[c][j];
                        kout[c][r][j] = v;
                        p[3 + c] += v * v;
                    }
                    // write fp16 k scratch (coalesced STG.64 per plane)
                    __half2 ha = __floats2half2_rn(kout[c][r][0], kout[c][r][1]);
                    __half2 hb = __floats2half2_rn(kout[c][r][2], kout[c][r][3]);
                    uint2 st;
                    st.x = *(unsigned*)&ha;
                    st.y = *(unsigned*)&hb;
                    *(uint2*)(gk + (size_t)c * N_PIX + o) = st;
                }
            }
#pragma unroll
            for (int c = 0; c < 3; c++)
#pragma unroll
                for (int j = 0; j < 4; j++) {
                    a0[c][j] = a1[c][j];
                    a1[c][j] = a2[c][j];
                    a2[c][j] = 0.f;
                }
        }
    }

    // ================= Q path (input fhigh, planar) =================
    {
        float cw[9], dw[27];
#pragma unroll
        for (int i = 0; i < 9; i++) cw[i] = qC[i];
#pragma unroll
        for (int i = 0; i < 27; i++) dw[i] = qD[i];

        float a0[3][4], a1[3][4], a2[3][4];
#pragma unroll
        for (int c = 0; c < 3; c++)
#pragma unroll
            for (int j = 0; j < 4; j++) { a0[c][j] = a1[c][j] = a2[c][j] = 0.f; }

#pragma unroll
        for (int iy = 0; iy < 6; iy++) {
            const int yin = y0 + iy - 1;
            const bool yok = (unsigned)yin < (unsigned)W_IMG;

            float hm[3][4];
#pragma unroll
            for (int c = 0; c < 3; c++)
#pragma unroll
                for (int j = 0; j < 4; j++) hm[c][j] = 0.f;

            if (yok) {
                const size_t o = (size_t)yin * W_IMG + px0;
                float4 f0 = *(const float4*)(fb + o);
                float4 f1 = *(const float4*)(fb + o + N_PIX);
                float4 f2 = *(const float4*)(fb + o + 2 * N_PIX);
                float g[4][3] = {{f0.x, f1.x, f2.x}, {f0.y, f1.y, f2.y},
                                 {f0.z, f1.z, f2.z}, {f0.w, f1.w, f2.w}};
#pragma unroll
                for (int j = 0; j < 4; j++)
#pragma unroll
                    for (int c = 0; c < 3; c++)
                        hm[c][j] = cw[c * 3] * g[j][0] + cw[c * 3 + 1] * g[j][1] + cw[c * 3 + 2] * g[j][2];
            }
            float he[3] = {0.f, 0.f, 0.f};
            if (yok && is_e && ex_ok) {
                const size_t o = (size_t)yin * W_IMG + ex;
                float g0 = fb[o], g1 = fb[o + N_PIX], g2 = fb[o + 2 * N_PIX];
#pragma unroll
                for (int c = 0; c < 3; c++)
                    he[c] = cw[c * 3] * g0 + cw[c * 3 + 1] * g1 + cw[c * 3 + 2] * g2;
            }
            float hl[3], hr[3];
#pragma unroll
            for (int c = 0; c < 3; c++) {
                hl[c] = __shfl_up_sync(0xffffffffu, hm[c][3], 1);
                hr[c] = __shfl_down_sync(0xffffffffu, hm[c][0], 1);
                if (lane == 0) hl[c] = he[c];
                if (lane == 31) hr[c] = he[c];
            }
#pragma unroll
            for (int c = 0; c < 3; c++)
#pragma unroll
                for (int j = 0; j < 4; j++) {
                    float L = j ? hm[c][j - 1] : hl[c];
                    float M_ = hm[c][j];
                    float R = (j < 3) ? hm[c][j + 1] : hr[c];
                    a0[c][j] += dw[c * 9 + 6] * L + dw[c * 9 + 7] * M_ + dw[c * 9 + 8] * R;
                    a1[c][j] += dw[c * 9 + 3] * L + dw[c * 9 + 4] * M_ + dw[c * 9 + 5] * R;
                    a2[c][j] += dw[c * 9 + 0] * L + dw[c * 9 + 1] * M_ + dw[c * 9 + 2] * R;
                }
            if (iy >= 2) {
                const int r = iy - 2;
#pragma unroll
                for (int c = 0; c < 3; c++)
#pragma unroll
                    for (int j = 0; j < 4; j++) {
                        float q = a0[c][j];
                        p[c] += q * q;
#pragma unroll
                        for (int d = 0; d < 3; d++)
                            p[6 + c * 3 + d] += q * kout[d][r][j];
                    }
            }
#pragma unroll
            for (int c = 0; c < 3; c++)
#pragma unroll
                for (int j = 0; j < 4; j++) {
                    a0[c][j] = a1[c][j];
                    a1[c][j] = a2[c][j];
                    a2[c][j] = 0.f;
                }
        }
    }

    // block reduce -> per-block partial
#pragma unroll
    for (int i = 0; i < 15; i++)
#pragma unroll
        for (int o = 16; o; o >>= 1)
            p[i] += __shfl_down_sync(0xffffffffu, p[i], o);
    if (lane == 0) {
#pragma unroll
        for (int i = 0; i < 15; i++) red[warp][i] = p[i];
    }
    __syncthreads();
    if (tid < 15) {
        float t = 0.f;
#pragma unroll
        for (int w2 = 0; w2 < NTH / 32; w2++) t += red[w2][tid];
        g_part[b][blockIdx.y * 8 + blockIdx.x][tid] = t;
    }
}

// ---------------------------------------------------------------------------
// k_out: prologue reduces 256 partials -> M (R7-proven); body = pure
// streaming map: read fp16 k planar (no halo, no conv), write out.
// 8 pixels per thread.
// ---------------------------------------------------------------------------
__global__ __launch_bounds__(NTH) void k_out(const float* __restrict__ proj_w,
                                             const float* __restrict__ proj_b,
                                             const float* __restrict__ temp,
                                             float* __restrict__ out) {
    __shared__ float sM[9];
    __shared__ float sred[NTH / 32][15];
    __shared__ float sstat[15];

    const int tid = threadIdx.x;
    const int b = blockIdx.z;
    const int warp = tid >> 5, lane = tid & 31;

    // --- prologue: reduce 256 partials x 15, compute M ---
    {
        float p[15];
        const float4* row = (const float4*)g_part[b][tid];
        float4 v0 = row[0], v1 = row[1], v2 = row[2], v3 = row[3];
        p[0] = v0.x;  p[1] = v0.y;  p[2] = v0.z;  p[3] = v0.w;
        p[4] = v1.x;  p[5] = v1.y;  p[6] = v1.z;  p[7] = v1.w;
        p[8] = v2.x;  p[9] = v2.y;  p[10] = v2.z; p[11] = v2.w;
        p[12] = v3.x; p[13] = v3.y; p[14] = v3.z;
#pragma unroll
        for (int i = 0; i < 15; i++)
#pragma unroll
            for (int o = 16; o; o >>= 1)
                p[i] += __shfl_down_sync(0xffffffffu, p[i], o);
        if (lane == 0) {
#pragma unroll
            for (int i = 0; i < 15; i++) sred[warp][i] = p[i];
        }
        __syncthreads();
        if (tid < 15) {
            float t = 0.f;
#pragma unroll
            for (int w2 = 0; w2 < NTH / 32; w2++) t += sred[w2][tid];
            sstat[tid] = t;
        }
        __syncthreads();
        if (tid == 0) {
            float T = temp[0];
            float nq[3], nk[3];
#pragma unroll
            for (int c = 0; c < 3; c++) {
                nq[c] = fmaxf(sqrtf(sstat[c]), 1e-12f);
                nk[c] = fmaxf(sqrtf(sstat[3 + c]), 1e-12f);
            }
            float a[3][3];
#pragma unroll
            for (int c = 0; c < 3; c++)
#pragma unroll
                for (int d = 0; d < 3; d++)
                    a[c][d] = sstat[6 + c * 3 + d] / (nq[c] * nk[d]) * T;
#pragma unroll
            for (int c = 0; c < 3; c++) {
                float mx = fmaxf(a[c][0], fmaxf(a[c][1], a[c][2]));
                float e0 = expf(a[c][0] - mx);
                float e1 = expf(a[c][1] - mx);
                float e2 = expf(a[c][2] - mx);
                float inv = 1.f / (e0 + e1 + e2);
                a[c][0] = e0 * inv; a[c][1] = e1 * inv; a[c][2] = e2 * inv;
            }
#pragma unroll
            for (int co = 0; co < 3; co++)
#pragma unroll
                for (int d = 0; d < 3; d++) {
                    float mm = 0.f;
#pragma unroll
                    for (int c = 0; c < 3; c++) mm += proj_w[co * 3 + c] * a[c][d];
                    sM[co * 3 + d] = mm;
                }
        }
        __syncthreads();
    }

    float m[9];
#pragma unroll
    for (int i = 0; i < 9; i++) m[i] = sM[i];
    const float b0 = proj_b[0], b1 = proj_b[1], b2 = proj_b[2];

    const size_t pix0 = ((size_t)blockIdx.x * NTH + tid) * 8;
    const __half* __restrict__ kb = g_k + (size_t)b * 3 * N_PIX;

    uint4 u0 = *(const uint4*)(kb + pix0);
    uint4 u1 = *(const uint4*)(kb + N_PIX + pix0);
    uint4 u2 = *(const uint4*)(kb + 2 * (size_t)N_PIX + pix0);

    float k0[8], k1[8], k2[8];
    {
        const unsigned* w0 = &u0.x;
        const unsigned* w1 = &u1.x;
        const unsigned* w2 = &u2.x;
#pragma unroll
        for (int i = 0; i < 4; i++) {
            float2 f0 = __half22float2(*(const __half2*)&w0[i]);
            float2 f1 = __half22float2(*(const __half2*)&w1[i]);
            float2 f2 = __half22float2(*(const __half2*)&w2[i]);
            k0[i * 2] = f0.x; k0[i * 2 + 1] = f0.y;
            k1[i * 2] = f1.x; k1[i * 2 + 1] = f1.y;
            k2[i * 2] = f2.x; k2[i * 2 + 1] = f2.y;
        }
    }

    float o[24];
#pragma unroll
    for (int j = 0; j < 8; j++) {
        o[j * 3 + 0] = m[0] * k0[j] + m[1] * k1[j] + m[2] * k2[j] + b0;
        o[j * 3 + 1] = m[3] * k0[j] + m[4] * k1[j] + m[5] * k2[j] + b1;
        o[j * 3 + 2] = m[6] * k0[j] + m[7] * k1[j] + m[8] * k2[j] + b2;
    }
    float4* q4 = (float4*)(out + ((size_t)b * N_PIX + pix0) * 3);
#pragma unroll
    for (int i = 0; i < 6; i++)
        q4[i] = make_float4(o[i * 4], o[i * 4 + 1], o[i * 4 + 2], o[i * 4 + 3]);
}

extern "C" void kernel_launch(void* const* d_in, const int* in_sizes, int n_in,
                              void* d_out, int out_size) {
    const float* x     = (const float*)d_in[0];
    const float* fhigh = (const float*)d_in[1];
    const float* qCw   = (const float*)d_in[2];
    const float* qdw   = (const float*)d_in[3];
    const float* kCw   = (const float*)d_in[4];
    const float* kdw   = (const float*)d_in[5];
    const float* projw = (const float*)d_in[6];
    const float* projb = (const float*)d_in[7];
    const float* temp  = (const float*)d_in[8];
    float* out = (float*)d_out;

    int B = in_sizes[0] / (N_PIX * 3);
    if (B > MAXB) B = MAXB;

    dim3 gridS(W_IMG / 128, W_IMG / 32, B);        // 256 blocks per batch
    k_stats<<<gridS, NTH>>>(x, fhigh, qCw, qdw, kCw, kdw);
    dim3 gridO(N_PIX / (NTH * 8), 1, B);           // 512 blocks per batch
    k_out<<<gridO, NTH>>>(projw, projb, temp, out);
}

// round 14
// speedup vs baseline: 1.3758x; 1.3758x over previous
#include <cuda_runtime.h>
#include <math.h>

#define W_IMG 1024
#define N_PIX (W_IMG * W_IMG)
#define MAXB 8
#define NTH 256
#define NBLK_STAT 256   // 8 x 32 blocks per batch

// per-block partial stats: [b][block][16]
// [0..2]=sum q_c^2, [3..5]=sum k_c^2, [6..14]=sum q_c*k_d
__device__ float g_part[MAXB][NBLK_STAT][16];

// ---------------------------------------------------------------------------
// k_stats: R6-proven 4x4 patch per thread (register kout). K path first,
// then Q path accumulating the 15 stats. Writes per-block partials only
// (no k_zero launch, no atomics, no finalize tail).
// ---------------------------------------------------------------------------
__global__ __launch_bounds__(NTH) void k_stats(const float* __restrict__ x,
                                               const float* __restrict__ fhigh,
                                               const float* __restrict__ qC,
                                               const float* __restrict__ qD,
                                               const float* __restrict__ kC,
                                               const float* __restrict__ kD) {
    __shared__ float red[NTH / 32][15];

    const int tid = threadIdx.x;
    const int b = blockIdx.z;
    const int warp = tid >> 5, lane = tid & 31;
    const int wx0 = blockIdx.x * 128;
    const int px0 = wx0 + lane * 4;
    const int y0 = blockIdx.y * 32 + warp * 4;

    const float* __restrict__ xb = x + (size_t)b * 3 * N_PIX;
    const float* __restrict__ fb = fhigh + (size_t)b * 3 * N_PIX;

    const bool is_e = (lane == 0) | (lane == 31);
    const int ex = (lane == 0) ? wx0 - 1 : wx0 + 128;
    const bool ex_ok = (unsigned)ex < (unsigned)W_IMG;

    float p[15];
#pragma unroll
    for (int i = 0; i < 15; i++) p[i] = 0.f;

    float kout[3][4][4];  // [ch][row][j]

    // ================= K path (input x, channels-last) =================
    {
        float cw[9], dw[27];
#pragma unroll
        for (int i = 0; i < 9; i++) cw[i] = kC[i];
#pragma unroll
        for (int i = 0; i < 27; i++) dw[i] = kD[i];

        float a0[3][4], a1[3][4], a2[3][4];
#pragma unroll
        for (int c = 0; c < 3; c++)
#pragma unroll
            for (int j = 0; j < 4; j++) { a0[c][j] = a1[c][j] = a2[c][j] = 0.f; }

#pragma unroll
        for (int iy = 0; iy < 6; iy++) {
            const int yin = y0 + iy - 1;
            const bool yok = (unsigned)yin < (unsigned)W_IMG;

            float hm[3][4];
#pragma unroll
            for (int c = 0; c < 3; c++)
#pragma unroll
                for (int j = 0; j < 4; j++) hm[c][j] = 0.f;

            if (yok) {
                const float4* p4 = (const float4*)(xb + (size_t)(yin * W_IMG + px0) * 3);
                float4 v0 = p4[0], v1 = p4[1], v2 = p4[2];
                float g[4][3] = {{v0.x, v0.y, v0.z}, {v0.w, v1.x, v1.y},
                                 {v1.z, v1.w, v2.x}, {v2.y, v2.z, v2.w}};
#pragma unroll
                for (int j = 0; j < 4; j++)
#pragma unroll
                    for (int c = 0; c < 3; c++)
                        hm[c][j] = cw[c * 3] * g[j][0] + cw[c * 3 + 1] * g[j][1] + cw[c * 3 + 2] * g[j][2];
            }
            float he[3] = {0.f, 0.f, 0.f};
            if (yok && is_e && ex_ok) {
                const float* pe = xb + (size_t)(yin * W_IMG + ex) * 3;
                float g0 = pe[0], g1 = pe[1], g2 = pe[2];
#pragma unroll
                for (int c = 0; c < 3; c++)
                    he[c] = cw[c * 3] * g0 + cw[c * 3 + 1] * g1 + cw[c * 3 + 2] * g2;
            }
            float hl[3], hr[3];
#pragma unroll
            for (int c = 0; c < 3; c++) {
                hl[c] = __shfl_up_sync(0xffffffffu, hm[c][3], 1);
                hr[c] = __shfl_down_sync(0xffffffffu, hm[c][0], 1);
                if (lane == 0) hl[c] = he[c];
                if (lane == 31) hr[c] = he[c];
            }
#pragma unroll
            for (int c = 0; c < 3; c++)
#pragma unroll
                for (int j = 0; j < 4; j++) {
                    float L = j ? hm[c][j - 1] : hl[c];
                    float M_ = hm[c][j];
                    float R = (j < 3) ? hm[c][j + 1] : hr[c];
                    a0[c][j] += dw[c * 9 + 6] * L + dw[c * 9 + 7] * M_ + dw[c * 9 + 8] * R;
                    a1[c][j] += dw[c * 9 + 3] * L + dw[c * 9 + 4] * M_ + dw[c * 9 + 5] * R;
                    a2[c][j] += dw[c * 9 + 0] * L + dw[c * 9 + 1] * M_ + dw[c * 9 + 2] * R;
                }
            if (iy >= 2) {
                const int r = iy - 2;
#pragma unroll
                for (int c = 0; c < 3; c++)
#pragma unroll
                    for (int j = 0; j < 4; j++) {
                        float v = a0[c][j];
                        kout[c][r][j] = v;
                        p[3 + c] += v * v;
                    }
            }
#pragma unroll
            for (int c = 0; c < 3; c++)
#pragma unroll
                for (int j = 0; j < 4; j++) {
                    a0[c][j] = a1[c][j];
                    a1[c][j] = a2[c][j];
                    a2[c][j] = 0.f;
                }
        }
    }

    // ================= Q path (input fhigh, planar) =================
    {
        float cw[9], dw[27];
#pragma unroll
        for (int i = 0; i < 9; i++) cw[i] = qC[i];
#pragma unroll
        for (int i = 0; i < 27; i++) dw[i] = qD[i];

        float a0[3][4], a1[3][4], a2[3][4];
#pragma unroll
        for (int c = 0; c < 3; c++)
#pragma unroll
            for (int j = 0; j < 4; j++) { a0[c][j] = a1[c][j] = a2[c][j] = 0.f; }

#pragma unroll
        for (int iy = 0; iy < 6; iy++) {
            const int yin = y0 + iy - 1;
            const bool yok = (unsigned)yin < (unsigned)W_IMG;

            float hm[3][4];
#pragma unroll
            for (int c = 0; c < 3; c++)
#pragma unroll
                for (int j = 0; j < 4; j++) hm[c][j] = 0.f;

            if (yok) {
                const size_t o = (size_t)yin * W_IMG + px0;
                float4 f0 = *(const float4*)(fb + o);
                float4 f1 = *(const float4*)(fb + o + N_PIX);
                float4 f2 = *(const float4*)(fb + o + 2 * N_PIX);
                float g[4][3] = {{f0.x, f1.x, f2.x}, {f0.y, f1.y, f2.y},
                                 {f0.z, f1.z, f2.z}, {f0.w, f1.w, f2.w}};
#pragma unroll
                for (int j = 0; j < 4; j++)
#pragma unroll
                    for (int c = 0; c < 3; c++)
                        hm[c][j] = cw[c * 3] * g[j][0] + cw[c * 3 + 1] * g[j][1] + cw[c * 3 + 2] * g[j][2];
            }
            float he[3] = {0.f, 0.f, 0.f};
            if (yok && is_e && ex_ok) {
                const size_t o = (size_t)yin * W_IMG + ex;
                float g0 = fb[o], g1 = fb[o + N_PIX], g2 = fb[o + 2 * N_PIX];
#pragma unroll
                for (int c = 0; c < 3; c++)
                    he[c] = cw[c * 3] * g0 + cw[c * 3 + 1] * g1 + cw[c * 3 + 2] * g2;
            }
            float hl[3], hr[3];
#pragma unroll
            for (int c = 0; c < 3; c++) {
                hl[c] = __shfl_up_sync(0xffffffffu, hm[c][3], 1);
                hr[c] = __shfl_down_sync(0xffffffffu, hm[c][0], 1);
                if (lane == 0) hl[c] = he[c];
                if (lane == 31) hr[c] = he[c];
            }
#pragma unroll
            for (int c = 0; c < 3; c++)
#pragma unroll
                for (int j = 0; j < 4; j++) {
                    float L = j ? hm[c][j - 1] : hl[c];
                    float M_ = hm[c][j];
                    float R = (j < 3) ? hm[c][j + 1] : hr[c];
                    a0[c][j] += dw[c * 9 + 6] * L + dw[c * 9 + 7] * M_ + dw[c * 9 + 8] * R;
                    a1[c][j] += dw[c * 9 + 3] * L + dw[c * 9 + 4] * M_ + dw[c * 9 + 5] * R;
                    a2[c][j] += dw[c * 9 + 0] * L + dw[c * 9 + 1] * M_ + dw[c * 9 + 2] * R;
                }
            if (iy >= 2) {
                const int r = iy - 2;
#pragma unroll
                for (int c = 0; c < 3; c++)
#pragma unroll
                    for (int j = 0; j < 4; j++) {
                        float q = a0[c][j];
                        p[c] += q * q;
#pragma unroll
                        for (int d = 0; d < 3; d++)
                            p[6 + c * 3 + d] += q * kout[d][r][j];
                    }
            }
#pragma unroll
            for (int c = 0; c < 3; c++)
#pragma unroll
                for (int j = 0; j < 4; j++) {
                    a0[c][j] = a1[c][j];
                    a1[c][j] = a2[c][j];
                    a2[c][j] = 0.f;
                }
        }
    }

    // block reduce -> per-block partial
#pragma unroll
    for (int i = 0; i < 15; i++)
#pragma unroll
        for (int o = 16; o; o >>= 1)
            p[i] += __shfl_down_sync(0xffffffffu, p[i], o);
    if (lane == 0) {
#pragma unroll
        for (int i = 0; i < 15; i++) red[warp][i] = p[i];
    }
    __syncthreads();
    if (tid < 15) {
        float t = 0.f;
#pragma unroll
        for (int w2 = 0; w2 < NTH / 32; w2++) t += red[w2][tid];
        g_part[b][blockIdx.y * 8 + blockIdx.x][tid] = t;
    }
}

// ---------------------------------------------------------------------------
// k_out: R7-proven exact kernel — prologue reduces 256 partials -> M;
// body = 4-wide x 8-tall patch k-conv + 3x3 map.
// ---------------------------------------------------------------------------
__global__ __launch_bounds__(NTH) void k_out(const float* __restrict__ x,
                                             const float* __restrict__ kC,
                                             const float* __restrict__ kD,
                                             const float* __restrict__ proj_w,
                                             const float* __restrict__ proj_b,
                                             const float* __restrict__ temp,
                                             float* __restrict__ out) {
    __shared__ float sM[9];
    __shared__ float sred[NTH / 32][15];
    __shared__ float sstat[15];

    const int tid = threadIdx.x;
    const int b = blockIdx.z;
    const int warp = tid >> 5, lane = tid & 31;

    // --- prologue: reduce 256 partials x 15, then compute M ---
    {
        float p[15];
        const float4* row = (const float4*)g_part[b][tid];
        float4 v0 = row[0], v1 = row[1], v2 = row[2], v3 = row[3];
        p[0] = v0.x;  p[1] = v0.y;  p[2] = v0.z;  p[3] = v0.w;
        p[4] = v1.x;  p[5] = v1.y;  p[6] = v1.z;  p[7] = v1.w;
        p[8] = v2.x;  p[9] = v2.y;  p[10] = v2.z; p[11] = v2.w;
        p[12] = v3.x; p[13] = v3.y; p[14] = v3.z;
#pragma unroll
        for (int i = 0; i < 15; i++)
#pragma unroll
            for (int o = 16; o; o >>= 1)
                p[i] += __shfl_down_sync(0xffffffffu, p[i], o);
        if (lane == 0) {
#pragma unroll
            for (int i = 0; i < 15; i++) sred[warp][i] = p[i];
        }
        __syncthreads();
        if (tid < 15) {
            float t = 0.f;
#pragma unroll
            for (int w2 = 0; w2 < NTH / 32; w2++) t += sred[w2][tid];
            sstat[tid] = t;
        }
        __syncthreads();
        if (tid == 0) {
            float T = temp[0];
            float nq[3], nk[3];
#pragma unroll
            for (int c = 0; c < 3; c++) {
                nq[c] = fmaxf(sqrtf(sstat[c]), 1e-12f);
                nk[c] = fmaxf(sqrtf(sstat[3 + c]), 1e-12f);
            }
            float a[3][3];
#pragma unroll
            for (int c = 0; c < 3; c++)
#pragma unroll
                for (int d = 0; d < 3; d++)
                    a[c][d] = sstat[6 + c * 3 + d] / (nq[c] * nk[d]) * T;
#pragma unroll
            for (int c = 0; c < 3; c++) {
                float mx = fmaxf(a[c][0], fmaxf(a[c][1], a[c][2]));
                float e0 = expf(a[c][0] - mx);
                float e1 = expf(a[c][1] - mx);
                float e2 = expf(a[c][2] - mx);
                float inv = 1.f / (e0 + e1 + e2);
                a[c][0] = e0 * inv; a[c][1] = e1 * inv; a[c][2] = e2 * inv;
            }
#pragma unroll
            for (int co = 0; co < 3; co++)
#pragma unroll
                for (int d = 0; d < 3; d++) {
                    float mm = 0.f;
#pragma unroll
                    for (int c = 0; c < 3; c++) mm += proj_w[co * 3 + c] * a[c][d];
                    sM[co * 3 + d] = mm;
                }
        }
        __syncthreads();
    }

    const int wx0 = blockIdx.x * 128;
    const int px0 = wx0 + lane * 4;
    const int y0 = blockIdx.y * 64 + warp * 8;

    const float* __restrict__ xb = x + (size_t)b * 3 * N_PIX;

    const bool is_e = (lane == 0) | (lane == 31);
    const int ex = (lane == 0) ? wx0 - 1 : wx0 + 128;
    const bool ex_ok = (unsigned)ex < (unsigned)W_IMG;

    float cw[9], dw[27];
#pragma unroll
    for (int i = 0; i < 9; i++) cw[i] = kC[i];
#pragma unroll
    for (int i = 0; i < 27; i++) dw[i] = kD[i];

    float m[9];
#pragma unroll
    for (int i = 0; i < 9; i++) m[i] = sM[i];
    const float b0 = proj_b[0], b1 = proj_b[1], b2 = proj_b[2];

    float a0[3][4], a1[3][4], a2[3][4];
#pragma unroll
    for (int c = 0; c < 3; c++)
#pragma unroll
        for (int j = 0; j < 4; j++) { a0[c][j] = a1[c][j] = a2[c][j] = 0.f; }

#pragma unroll
    for (int iy = 0; iy < 10; iy++) {
        const int yin = y0 + iy - 1;
        const bool yok = (unsigned)yin < (unsigned)W_IMG;

        float hm[3][4];
#pragma unroll
        for (int c = 0; c < 3; c++)
#pragma unroll
            for (int j = 0; j < 4; j++) hm[c][j] = 0.f;

        if (yok) {
            const float4* p4 = (const float4*)(xb + (size_t)(yin * W_IMG + px0) * 3);
            float4 v0 = p4[0], v1 = p4[1], v2 = p4[2];
            float g[4][3] = {{v0.x, v0.y, v0.z}, {v0.w, v1.x, v1.y},
                             {v1.z, v1.w, v2.x}, {v2.y, v2.z, v2.w}};
#pragma unroll
            for (int j = 0; j < 4; j++)
#pragma unroll
                for (int c = 0; c < 3; c++)
                    hm[c][j] = cw[c * 3] * g[j][0] + cw[c * 3 + 1] * g[j][1] + cw[c * 3 + 2] * g[j][2];
        }
        float he[3] = {0.f, 0.f, 0.f};
        if (yok && is_e && ex_ok) {
            const float* pe = xb + (size_t)(yin * W_IMG + ex) * 3;
            float g0 = pe[0], g1 = pe[1], g2 = pe[2];
#pragma unroll
            for (int c = 0; c < 3; c++)
                he[c] = cw[c * 3] * g0 + cw[c * 3 + 1] * g1 + cw[c * 3 + 2] * g2;
        }
        float hl[3], hr[3];
#pragma unroll
        for (int c = 0; c < 3; c++) {
            hl[c] = __shfl_up_sync(0xffffffffu, hm[c][3], 1);
            hr[c] = __shfl_down_sync(0xffffffffu, hm[c][0], 1);
            if (lane == 0) hl[c] = he[c];
            if (lane == 31) hr[c] = he[c];
        }
#pragma unroll
        for (int c = 0; c < 3; c++)
#pragma unroll
            for (int j = 0; j < 4; j++) {
                float L = j ? hm[c][j - 1] : hl[c];
                float M_ = hm[c][j];
                float R = (j < 3) ? hm[c][j + 1] : hr[c];
                a0[c][j] += dw[c * 9 + 6] * L + dw[c * 9 + 7] * M_ + dw[c * 9 + 8] * R;
                a1[c][j] += dw[c * 9 + 3] * L + dw[c * 9 + 4] * M_ + dw[c * 9 + 5] * R;
                a2[c][j] += dw[c * 9 + 0] * L + dw[c * 9 + 1] * M_ + dw[c * 9 + 2] * R;
            }
        if (iy >= 2) {
            const int yout = y0 + iy - 2;
            float o[12];
#pragma unroll
            for (int j = 0; j < 4; j++) {
                float k0 = a0[0][j], k1 = a0[1][j], k2 = a0[2][j];
                o[j * 3 + 0] = m[0] * k0 + m[1] * k1 + m[2] * k2 + b0;
                o[j * 3 + 1] = m[3] * k0 + m[4] * k1 + m[5] * k2 + b1;
                o[j * 3 + 2] = m[6] * k0 + m[7] * k1 + m[8] * k2 + b2;
            }
            float4* q4 = (float4*)(out + ((size_t)b * N_PIX + (size_t)yout * W_IMG + px0) * 3);
            q4[0] = make_float4(o[0], o[1], o[2], o[3]);
            q4[1] = make_float4(o[4], o[5], o[6], o[7]);
            q4[2] = make_float4(o[8], o[9], o[10], o[11]);
        }
#pragma unroll
        for (int c = 0; c < 3; c++)
#pragma unroll
            for (int j = 0; j < 4; j++) {
                a0[c][j] = a1[c][j];
                a1[c][j] = a2[c][j];
                a2[c][j] = 0.f;
            }
    }
}

extern "C" void kernel_launch(void* const* d_in, const int* in_sizes, int n_in,
                              void* d_out, int out_size) {
    const float* x     = (const float*)d_in[0];
    const float* fhigh = (const float*)d_in[1];
    const float* qCw   = (const float*)d_in[2];
    const float* qdw   = (const float*)d_in[3];
    const float* kCw   = (const float*)d_in[4];
    const float* kdw   = (const float*)d_in[5];
    const float* projw = (const float*)d_in[6];
    const float* projb = (const float*)d_in[7];
    const float* temp  = (const float*)d_in[8];
    float* out = (float*)d_out;

    int B = in_sizes[0] / (N_PIX * 3);
    if (B > MAXB) B = MAXB;

    dim3 gridS(W_IMG / 128, W_IMG / 32, B);   // 256 blocks per batch
    k_stats<<<gridS, NTH>>>(x, fhigh, qCw, qdw, kCw, kdw);
    dim3 gridO(W_IMG / 128, W_IMG / 64, B);   // 128 blocks per batch
    k_out<<<gridO, NTH>>>(x, kCw, kdw, projw, projb, temp, out);
}

// round 15
// speedup vs baseline: 1.3840x; 1.0059x over previous
#include <cuda_runtime.h>
#include <cuda_fp16.h>
#include <math.h>

#define W_IMG 1024
#define N_PIX (W_IMG * W_IMG)
#define MAXB 8
#define NTH 256

// stats per batch: [0..2]=sum q_c^2, [3..5]=sum k_c^2, [6..14]=sum q_c*k_d
__device__ float g_stats[MAXB][16];

// ---------------------------------------------------------------------------
// k_stats: R6-proven 4x4 patch per thread; kout patch packed as fp16x2
// (24 regs instead of 48). K path first, then Q path accumulating 15 stats
// in fp32. atomicAdd into g_stats (zeroed by a memset graph node).
// ---------------------------------------------------------------------------
__global__ __launch_bounds__(NTH) void k_stats(const float* __restrict__ x,
                                               const float* __restrict__ fhigh,
                                               const float* __restrict__ qC,
                                               const float* __restrict__ qD,
                                               const float* __restrict__ kC,
                                               const float* __restrict__ kD) {
    __shared__ float red[NTH / 32][15];

    const int tid = threadIdx.x;
    const int b = blockIdx.z;
    const int warp = tid >> 5, lane = tid & 31;
    const int wx0 = blockIdx.x * 128;
    const int px0 = wx0 + lane * 4;
    const int y0 = blockIdx.y * 32 + warp * 4;

    const float* __restrict__ xb = x + (size_t)b * 3 * N_PIX;
    const float* __restrict__ fb = fhigh + (size_t)b * 3 * N_PIX;

    const bool is_e = (lane == 0) | (lane == 31);
    const int ex = (lane == 0) ? wx0 - 1 : wx0 + 128;
    const bool ex_ok = (unsigned)ex < (unsigned)W_IMG;

    float p[15];
#pragma unroll
    for (int i = 0; i < 15; i++) p[i] = 0.f;

    __half2 kout[3][4][2];  // [ch][row][pair] : 4 pixels packed as 2x half2

    // ================= K path (input x, channels-last) =================
    {
        float cw[9], dw[27];
#pragma unroll
        for (int i = 0; i < 9; i++) cw[i] = kC[i];
#pragma unroll
        for (int i = 0; i < 27; i++) dw[i] = kD[i];

        float a0[3][4], a1[3][4], a2[3][4];
#pragma unroll
        for (int c = 0; c < 3; c++)
#pragma unroll
            for (int j = 0; j < 4; j++) { a0[c][j] = a1[c][j] = a2[c][j] = 0.f; }

#pragma unroll
        for (int iy = 0; iy < 6; iy++) {
            const int yin = y0 + iy - 1;
            const bool yok = (unsigned)yin < (unsigned)W_IMG;

            float hm[3][4];
#pragma unroll
            for (int c = 0; c < 3; c++)
#pragma unroll
                for (int j = 0; j < 4; j++) hm[c][j] = 0.f;

            if (yok) {
                const float4* p4 = (const float4*)(xb + (size_t)(yin * W_IMG + px0) * 3);
                float4 v0 = p4[0], v1 = p4[1], v2 = p4[2];
                float g[4][3] = {{v0.x, v0.y, v0.z}, {v0.w, v1.x, v1.y},
                                 {v1.z, v1.w, v2.x}, {v2.y, v2.z, v2.w}};
#pragma unroll
                for (int j = 0; j < 4; j++)
#pragma unroll
                    for (int c = 0; c < 3; c++)
                        hm[c][j] = cw[c * 3] * g[j][0] + cw[c * 3 + 1] * g[j][1] + cw[c * 3 + 2] * g[j][2];
            }
            float he[3] = {0.f, 0.f, 0.f};
            if (yok && is_e && ex_ok) {
                const float* pe = xb + (size_t)(yin * W_IMG + ex) * 3;
                float g0 = pe[0], g1 = pe[1], g2 = pe[2];
#pragma unroll
                for (int c = 0; c < 3; c++)
                    he[c] = cw[c * 3] * g0 + cw[c * 3 + 1] * g1 + cw[c * 3 + 2] * g2;
            }
            float hl[3], hr[3];
#pragma unroll
            for (int c = 0; c < 3; c++) {
                hl[c] = __shfl_up_sync(0xffffffffu, hm[c][3], 1);
                hr[c] = __shfl_down_sync(0xffffffffu, hm[c][0], 1);
                if (lane == 0) hl[c] = he[c];
                if (lane == 31) hr[c] = he[c];
            }
#pragma unroll
            for (int c = 0; c < 3; c++)
#pragma unroll
                for (int j = 0; j < 4; j++) {
                    float L = j ? hm[c][j - 1] : hl[c];
                    float M_ = hm[c][j];
                    float R = (j < 3) ? hm[c][j + 1] : hr[c];
                    a0[c][j] += dw[c * 9 + 6] * L + dw[c * 9 + 7] * M_ + dw[c * 9 + 8] * R;
                    a1[c][j] += dw[c * 9 + 3] * L + dw[c * 9 + 4] * M_ + dw[c * 9 + 5] * R;
                    a2[c][j] += dw[c * 9 + 0] * L + dw[c * 9 + 1] * M_ + dw[c * 9 + 2] * R;
                }
            if (iy >= 2) {
                const int r = iy - 2;
#pragma unroll
                for (int c = 0; c < 3; c++) {
#pragma unroll
                    for (int j = 0; j < 4; j++) {
                        float v = a0[c][j];
                        p[3 + c] += v * v;
                    }
                    kout[c][r][0] = __floats2half2_rn(a0[c][0], a0[c][1]);
                    kout[c][r][1] = __floats2half2_rn(a0[c][2], a0[c][3]);
                }
            }
#pragma unroll
            for (int c = 0; c < 3; c++)
#pragma unroll
                for (int j = 0; j < 4; j++) {
                    a0[c][j] = a1[c][j];
                    a1[c][j] = a2[c][j];
                    a2[c][j] = 0.f;
                }
        }
    }

    // ================= Q path (input fhigh, planar) =================
    {
        float cw[9], dw[27];
#pragma unroll
        for (int i = 0; i < 9; i++) cw[i] = qC[i];
#pragma unroll
        for (int i = 0; i < 27; i++) dw[i] = qD[i];

        float a0[3][4], a1[3][4], a2[3][4];
#pragma unroll
        for (int c = 0; c < 3; c++)
#pragma unroll
            for (int j = 0; j < 4; j++) { a0[c][j] = a1[c][j] = a2[c][j] = 0.f; }

#pragma unroll
        for (int iy = 0; iy < 6; iy++) {
            const int yin = y0 + iy - 1;
            const bool yok = (unsigned)yin < (unsigned)W_IMG;

            float hm[3][4];
#pragma unroll
            for (int c = 0; c < 3; c++)
#pragma unroll
                for (int j = 0; j < 4; j++) hm[c][j] = 0.f;

            if (yok) {
                const size_t o = (size_t)yin * W_IMG + px0;
                float4 f0 = *(const float4*)(fb + o);
                float4 f1 = *(const float4*)(fb + o + N_PIX);
                float4 f2 = *(const float4*)(fb + o + 2 * N_PIX);
                float g[4][3] = {{f0.x, f1.x, f2.x}, {f0.y, f1.y, f2.y},
                                 {f0.z, f1.z, f2.z}, {f0.w, f1.w, f2.w}};
#pragma unroll
                for (int j = 0; j < 4; j++)
#pragma unroll
                    for (int c = 0; c < 3; c++)
                        hm[c][j] = cw[c * 3] * g[j][0] + cw[c * 3 + 1] * g[j][1] + cw[c * 3 + 2] * g[j][2];
            }
            float he[3] = {0.f, 0.f, 0.f};
            if (yok && is_e && ex_ok) {
                const size_t o = (size_t)yin * W_IMG + ex;
                float g0 = fb[o], g1 = fb[o + N_PIX], g2 = fb[o + 2 * N_PIX];
#pragma unroll
                for (int c = 0; c < 3; c++)
                    he[c] = cw[c * 3] * g0 + cw[c * 3 + 1] * g1 + cw[c * 3 + 2] * g2;
            }
            float hl[3], hr[3];
#pragma unroll
            for (int c = 0; c < 3; c++) {
                hl[c] = __shfl_up_sync(0xffffffffu, hm[c][3], 1);
                hr[c] = __shfl_down_sync(0xffffffffu, hm[c][0], 1);
                if (lane == 0) hl[c] = he[c];
                if (lane == 31) hr[c] = he[c];
            }
#pragma unroll
            for (int c = 0; c < 3; c++)
#pragma unroll
                for (int j = 0; j < 4; j++) {
                    float L = j ? hm[c][j - 1] : hl[c];
                    float M_ = hm[c][j];
                    float R = (j < 3) ? hm[c][j + 1] : hr[c];
                    a0[c][j] += dw[c * 9 + 6] * L + dw[c * 9 + 7] * M_ + dw[c * 9 + 8] * R;
                    a1[c][j] += dw[c * 9 + 3] * L + dw[c * 9 + 4] * M_ + dw[c * 9 + 5] * R;
                    a2[c][j] += dw[c * 9 + 0] * L + dw[c * 9 + 1] * M_ + dw[c * 9 + 2] * R;
                }
            if (iy >= 2) {
                const int r = iy - 2;
                // unpack this row's k values once
                float kv[3][4];
#pragma unroll
                for (int d = 0; d < 3; d++) {
                    float2 f01 = __half22float2(kout[d][r][0]);
                    float2 f23 = __half22float2(kout[d][r][1]);
                    kv[d][0] = f01.x; kv[d][1] = f01.y;
                    kv[d][2] = f23.x; kv[d][3] = f23.y;
                }
#pragma unroll
                for (int c = 0; c < 3; c++)
#pragma unroll
                    for (int j = 0; j < 4; j++) {
                        float q = a0[c][j];
                        p[c] += q * q;
#pragma unroll
                        for (int d = 0; d < 3; d++)
                            p[6 + c * 3 + d] += q * kv[d][j];
                    }
            }
#pragma unroll
            for (int c = 0; c < 3; c++)
#pragma unroll
                for (int j = 0; j < 4; j++) {
                    a0[c][j] = a1[c][j];
                    a1[c][j] = a2[c][j];
                    a2[c][j] = 0.f;
                }
        }
    }

    // reduce
#pragma unroll
    for (int i = 0; i < 15; i++)
#pragma unroll
        for (int o = 16; o; o >>= 1)
            p[i] += __shfl_down_sync(0xffffffffu, p[i], o);
    if (lane == 0) {
#pragma unroll
        for (int i = 0; i < 15; i++) red[warp][i] = p[i];
    }
    __syncthreads();
    if (tid < 15) {
        float t = 0.f;
#pragma unroll
        for (int w2 = 0; w2 < NTH / 32; w2++) t += red[w2][tid];
        atomicAdd(&g_stats[b][tid], t);
    }
}

// ---------------------------------------------------------------------------
// k_out: R6-proven exact kernel — cheap prologue (1 thread computes M from
// g_stats into smem); body = 4-wide x 8-tall patch k-conv + 3x3 map.
// ---------------------------------------------------------------------------
__global__ __launch_bounds__(NTH) void k_out(const float* __restrict__ x,
                                             const float* __restrict__ kC,
                                             const float* __restrict__ kD,
                                             const float* __restrict__ proj_w,
                                             const float* __restrict__ proj_b,
                                             const float* __restrict__ temp,
                                             float* __restrict__ out) {
    __shared__ float sM[9];

    const int b = blockIdx.z;

    if (threadIdx.x == 0) {
        float T = temp[0];
        float nq[3], nk[3];
#pragma unroll
        for (int c = 0; c < 3; c++) {
            nq[c] = fmaxf(sqrtf(g_stats[b][c]), 1e-12f);
            nk[c] = fmaxf(sqrtf(g_stats[b][3 + c]), 1e-12f);
        }
        float a[3][3];
#pragma unroll
        for (int c = 0; c < 3; c++)
#pragma unroll
            for (int d = 0; d < 3; d++)
                a[c][d] = g_stats[b][6 + c * 3 + d] / (nq[c] * nk[d]) * T;
#pragma unroll
        for (int c = 0; c < 3; c++) {
            float mx = fmaxf(a[c][0], fmaxf(a[c][1], a[c][2]));
            float e0 = expf(a[c][0] - mx);
            float e1 = expf(a[c][1] - mx);
            float e2 = expf(a[c][2] - mx);
            float inv = 1.f / (e0 + e1 + e2);
            a[c][0] = e0 * inv; a[c][1] = e1 * inv; a[c][2] = e2 * inv;
        }
#pragma unroll
        for (int co = 0; co < 3; co++)
#pragma unroll
            for (int d = 0; d < 3; d++) {
                float mm = 0.f;
#pragma unroll
                for (int c = 0; c < 3; c++) mm += proj_w[co * 3 + c] * a[c][d];
                sM[co * 3 + d] = mm;
            }
    }
    __syncthreads();

    const int warp = threadIdx.x >> 5, lane = threadIdx.x & 31;
    const int wx0 = blockIdx.x * 128;
    const int px0 = wx0 + lane * 4;
    const int y0 = blockIdx.y * 64 + warp * 8;

    const float* __restrict__ xb = x + (size_t)b * 3 * N_PIX;

    const bool is_e = (lane == 0) | (lane == 31);
    const int ex = (lane == 0) ? wx0 - 1 : wx0 + 128;
    const bool ex_ok = (unsigned)ex < (unsigned)W_IMG;

    float cw[9], dw[27];
#pragma unroll
    for (int i = 0; i < 9; i++) cw[i] = kC[i];
#pragma unroll
    for (int i = 0; i < 27; i++) dw[i] = kD[i];

    float m[9];
#pragma unroll
    for (int i = 0; i < 9; i++) m[i] = sM[i];
    const float b0 = proj_b[0], b1 = proj_b[1], b2 = proj_b[2];

    float a0[3][4], a1[3][4], a2[3][4];
#pragma unroll
    for (int c = 0; c < 3; c++)
#pragma unroll
        for (int j = 0; j < 4; j++) { a0[c][j] = a1[c][j] = a2[c][j] = 0.f; }

#pragma unroll
    for (int iy = 0; iy < 10; iy++) {
        const int yin = y0 + iy - 1;
        const bool yok = (unsigned)yin < (unsigned)W_IMG;

        float hm[3][4];
#pragma unroll
        for (int c = 0; c < 3; c++)
#pragma unroll
            for (int j = 0; j < 4; j++) hm[c][j] = 0.f;

        if (yok) {
            const float4* p4 = (const float4*)(xb + (size_t)(yin * W_IMG + px0) * 3);
            float4 v0 = p4[0], v1 = p4[1], v2 = p4[2];
            float g[4][3] = {{v0.x, v0.y, v0.z}, {v0.w, v1.x, v1.y},
                             {v1.z, v1.w, v2.x}, {v2.y, v2.z, v2.w}};
#pragma unroll
            for (int j = 0; j < 4; j++)
#pragma unroll
                for (int c = 0; c < 3; c++)
                    hm[c][j] = cw[c * 3] * g[j][0] + cw[c * 3 + 1] * g[j][1] + cw[c * 3 + 2] * g[j][2];
        }
        float he[3] = {0.f, 0.f, 0.f};
        if (yok && is_e && ex_ok) {
            const float* pe = xb + (size_t)(yin * W_IMG + ex) * 3;
            float g0 = pe[0], g1 = pe[1], g2 = pe[2];
#pragma unroll
            for (int c = 0; c < 3; c++)
                he[c] = cw[c * 3] * g0 + cw[c * 3 + 1] * g1 + cw[c * 3 + 2] * g2;
        }
        float hl[3], hr[3];
#pragma unroll
        for (int c = 0; c < 3; c++) {
            hl[c] = __shfl_up_sync(0xffffffffu, hm[c][3], 1);
            hr[c] = __shfl_down_sync(0xffffffffu, hm[c][0], 1);
            if (lane == 0) hl[c] = he[c];
            if (lane == 31) hr[c] = he[c];
        }
#pragma unroll
        for (int c = 0; c < 3; c++)
#pragma unroll
            for (int j = 0; j < 4; j++) {
                float L = j ? hm[c][j - 1] : hl[c];
                float M_ = hm[c][j];
                float R = (j < 3) ? hm[c][j + 1] : hr[c];
                a0[c][j] += dw[c * 9 + 6] * L + dw[c * 9 + 7] * M_ + dw[c * 9 + 8] * R;
                a1[c][j] += dw[c * 9 + 3] * L + dw[c * 9 + 4] * M_ + dw[c * 9 + 5] * R;
                a2[c][j] += dw[c * 9 + 0] * L + dw[c * 9 + 1] * M_ + dw[c * 9 + 2] * R;
            }
        if (iy >= 2) {
            const int yout = y0 + iy - 2;
            float o[12];
#pragma unroll
            for (int j = 0; j < 4; j++) {
                float k0 = a0[0][j], k1 = a0[1][j], k2 = a0[2][j];
                o[j * 3 + 0] = m[0] * k0 + m[1] * k1 + m[2] * k2 + b0;
                o[j * 3 + 1] = m[3] * k0 + m[4] * k1 + m[5] * k2 + b1;
                o[j * 3 + 2] = m[6] * k0 + m[7] * k1 + m[8] * k2 + b2;
            }
            float4* q4 = (float4*)(out + ((size_t)b * N_PIX + (size_t)yout * W_IMG + px0) * 3);
            q4[0] = make_float4(o[0], o[1], o[2], o[3]);
            q4[1] = make_float4(o[4], o[5], o[6], o[7]);
            q4[2] = make_float4(o[8], o[9], o[10], o[11]);
        }
#pragma unroll
        for (int c = 0; c < 3; c++)
#pragma unroll
            for (int j = 0; j < 4; j++) {
                a0[c][j] = a1[c][j];
                a1[c][j] = a2[c][j];
                a2[c][j] = 0.f;
            }
    }
}

extern "C" void kernel_launch(void* const* d_in, const int* in_sizes, int n_in,
                              void* d_out, int out_size) {
    const float* x     = (const float*)d_in[0];
    const float* fhigh = (const float*)d_in[1];
    const float* qCw   = (const float*)d_in[2];
    const float* qdw   = (const float*)d_in[3];
    const float* kCw   = (const float*)d_in[4];
    const float* kdw   = (const float*)d_in[5];
    const float* projw = (const float*)d_in[6];
    const float* projb = (const float*)d_in[7];
    const float* temp  = (const float*)d_in[8];
    float* out = (float*)d_out;

    int B = in_sizes[0] / (N_PIX * 3);
    if (B > MAXB) B = MAXB;

    // zero the stats accumulator via a memset node (cheaper than a kernel)
    void* stats_addr = nullptr;
    cudaGetSymbolAddress(&stats_addr, g_stats);
    cudaMemsetAsync(stats_addr, 0, sizeof(float) * MAXB * 16, 0);

    dim3 gridS(W_IMG / 128, W_IMG / 32, B);   // 256 blocks per batch
    k_stats<<<gridS, NTH>>>(x, fhigh, qCw, qdw, kCw, kdw);
    dim3 gridO(W_IMG / 128, W_IMG / 64, B);   // 128 blocks per batch
    k_out<<<gridO, NTH>>>(x, kCw, kdw, projw, projb, temp, out);
}